// round 11
// baseline (speedup 1.0000x reference)
#include <cuda_runtime.h>
#include <cstdint>

#define S 8192
#define H 1024
#define NSM 128
#define SCAN_THREADS 544   // 16 dot-warps + finalizer warp 16 (highest wid)
#define NREP 8             // packet-line replicas (consumers split by bid&7)

// Scratch: input-side gate projections gx[S][3H].
__device__ float g_gx[(size_t)S * 3 * H];
// h-exchange lines, replicated x8 and double buffered:
//   [rep][slot][producer][32 floats] = one 128B line per (rep,slot,producer).
// Three self-validating 16B packets per line:
//   [tag h0 h1 h2] [tag h3 h4 h5] [tag h6 h7 pad]  (tag = step+1 as uint bits)
__device__ __align__(128) float g_hline[NREP * 2 * NSM * 32];

// ---------------------------------------------------------------------------
// packed fp32x2 helpers (sm_103a FFMA2 path)
// ---------------------------------------------------------------------------
__device__ __forceinline__ unsigned long long pack2(float lo, float hi) {
    unsigned long long r;
    asm("mov.b64 %0, {%1, %2};" : "=l"(r) : "f"(lo), "f"(hi));
    return r;
}
__device__ __forceinline__ unsigned long long ffma2(unsigned long long a,
                                                    unsigned long long b,
                                                    unsigned long long c) {
    unsigned long long d;
    asm("fma.rn.f32x2 %0, %1, %2, %3;" : "=l"(d) : "l"(a), "l"(b), "l"(c));
    return d;
}
__device__ __forceinline__ float hsum2(unsigned long long a) {
    float lo, hi;
    asm("mov.b64 {%0, %1}, %2;" : "=f"(lo), "=f"(hi) : "l"(a));
    return lo + hi;
}

// ---------------------------------------------------------------------------
// Kernel 1: gx = inp @ W_ih^T + b_ih  (fp32 GEMM, 128x128x16 tiles, FFMA2)
// Block (0,0) also clears the h-line buffer for this graph replay.
// ---------------------------------------------------------------------------
__global__ __launch_bounds__(256) void gemm_gx_kernel(
    const float* __restrict__ A,
    const float* __restrict__ Wih,
    const float* __restrict__ bih)
{
    __shared__ __align__(16) float As[16][132];
    __shared__ __align__(16) float Bs[16][132];

    const int tid = threadIdx.x;
    if (blockIdx.x == 0 && blockIdx.y == 0) {
        // NREP*2*128*32 = 65536 floats = 16384 float4; 256 threads x 64 each
        float4 z = make_float4(0.f, 0.f, 0.f, 0.f);
        float4* dst = (float4*)g_hline + tid;
#pragma unroll
        for (int q = 0; q < 64; ++q) dst[q * 256] = z;
    }

    const int m0 = blockIdx.y * 128;
    const int n0 = blockIdx.x * 128;
    const int tx = tid & 15;
    const int ty = tid >> 4;

    unsigned long long acc2[8][4];
#pragma unroll
    for (int i = 0; i < 8; ++i)
#pragma unroll
        for (int q = 0; q < 4; ++q) acc2[i][q] = 0ULL;

    for (int kt = 0; kt < 1024; kt += 16) {
#pragma unroll
        for (int r = 0; r < 2; ++r) {
            int idx = tid + r * 256;
            int row = idx >> 2;
            int kq  = idx & 3;
            float4 v = *(const float4*)(A + (size_t)(m0 + row) * 1024 + kt + kq * 4);
            As[kq * 4 + 0][row] = v.x;
            As[kq * 4 + 1][row] = v.y;
            As[kq * 4 + 2][row] = v.z;
            As[kq * 4 + 3][row] = v.w;
        }
#pragma unroll
        for (int r = 0; r < 2; ++r) {
            int idx = tid + r * 256;
            int n  = idx >> 2;
            int kq = idx & 3;
            float4 v = *(const float4*)(Wih + (size_t)(n0 + n) * 1024 + kt + kq * 4);
            Bs[kq * 4 + 0][n] = v.x;
            Bs[kq * 4 + 1][n] = v.y;
            Bs[kq * 4 + 2][n] = v.z;
            Bs[kq * 4 + 3][n] = v.w;
        }
        __syncthreads();

#pragma unroll
        for (int k = 0; k < 16; ++k) {
            float4 b0 = *(const float4*)&Bs[k][tx * 8];
            float4 b1 = *(const float4*)&Bs[k][tx * 8 + 4];
            unsigned long long rb2[4];
            rb2[0] = pack2(b0.x, b0.y);
            rb2[1] = pack2(b0.z, b0.w);
            rb2[2] = pack2(b1.x, b1.y);
            rb2[3] = pack2(b1.z, b1.w);
#pragma unroll
            for (int i = 0; i < 8; ++i) {
                float a = As[k][ty * 8 + i];
                unsigned long long a2 = pack2(a, a);
#pragma unroll
                for (int q = 0; q < 4; ++q)
                    acc2[i][q] = ffma2(a2, rb2[q], acc2[i][q]);
            }
        }
        __syncthreads();
    }

#pragma unroll
    for (int i = 0; i < 8; ++i) {
        size_t rowoff = (size_t)(m0 + ty * 8 + i) * 3072 + n0 + tx * 8;
#pragma unroll
        for (int jq = 0; jq < 2; ++jq) {
            float lo0, hi0, lo1, hi1;
            asm("mov.b64 {%0, %1}, %2;" : "=f"(lo0), "=f"(hi0) : "l"(acc2[i][jq * 2 + 0]));
            asm("mov.b64 {%0, %1}, %2;" : "=f"(lo1), "=f"(hi1) : "l"(acc2[i][jq * 2 + 1]));
            float4 v;
            v.x = lo0 + bih[n0 + tx * 8 + jq * 4 + 0];
            v.y = hi0 + bih[n0 + tx * 8 + jq * 4 + 1];
            v.z = lo1 + bih[n0 + tx * 8 + jq * 4 + 2];
            v.w = hi1 + bih[n0 + tx * 8 + jq * 4 + 3];
            *(float4*)(g_gx + rowoff + jq * 4) = v;
        }
    }
}

// ---------------------------------------------------------------------------
// Kernel 2: persistent GRU scan. 128 CTAs (one per SM), 544 threads.
//
// R11 change vs R10 (which was the confirmed big win): packet-line replicas
// NREP 4 -> 8. Finalizer lanes 0..23 publish 24 packets (3 per replica x 8,
// one STG.128 each, fully parallel). Consumer CTA bid polls replica
// (bid & 7): consumers per physical 128B line drop 32 -> 16, per-L2-slice
// poll demand ~0.16 sect/cyc and burst queue depth halves again.
//
// Protocol recap: self-validating 16B packets [tag|3 floats] written with
// st.volatile.v4 (tag+data visible atomically, no fence); consumer leaders
// do a fused poll+fetch (the detecting load already carries the h data),
// per-lane predicated. Siblings parked at per-chunk named barriers.
// Warp 16 = finalizer (highest wid = arbiter priority). Double buffer on
// t&1; skew<=1 so exact ==t tag check suffices.
// ---------------------------------------------------------------------------
__global__ __launch_bounds__(SCAN_THREADS, 1) void gru_scan_kernel(
    const float* __restrict__ Whh,
    const float* __restrict__ bhh,
    float* __restrict__ out)
{
    const int tid  = threadIdx.x;
    const int warp = tid >> 5;
    const int lane = tid & 31;
    const int bid  = blockIdx.x;
    const int obase = bid * 8;

    __shared__ __align__(16) float s_h[4][256];        // per-chunk h relay
    __shared__ __align__(16) float partials[2][24][36];

    const bool isfin = (warp == 16);
    const int c = warp & 3;              // k-chunk (0..3): leaders on SMSP 0..3
    const int g = warp >> 2;             // row-group (0..3)
    const int k0 = c * 256 + lane * 8;
    const int p  = c * 32 + lane;        // producer this lane covers (g==0)
    const int myrep = bid & (NREP - 1);  // replica this CTA polls

    // ---- dot-warp setup: 6 gate-rows x 8 cols of W_hh, packed f32x2 ----
    unsigned long long w2[6][4];
    if (!isfin) {
#pragma unroll
        for (int j = 0; j < 6; ++j) {
            int gr  = g * 6 + j;                          // 0..23
            int row = (gr >> 3) * H + obase + (gr & 7);   // gate*H + out idx
            const float4* pw = (const float4*)(Whh + (size_t)row * H + k0);
            float4 a = pw[0], b = pw[1];
            w2[j][0] = pack2(a.x, a.y);
            w2[j][1] = pack2(a.z, a.w);
            w2[j][2] = pack2(b.x, b.y);
            w2[j][3] = pack2(b.z, b.w);
        }
    }

    // ---- finalizer setup ----
    const int o = lane & 7;
    float bh = 0.f;
    if (isfin && lane < 24) bh = bhh[(lane >> 3) * H + obase + o];
    float hprev = 0.f;                   // lanes 0..7 carry h for their dim
    const size_t gx_lane_off = (size_t)(lane >> 3) * H + obase + o;

    for (int t = 0; t < S; ++t) {
        const int buf = t & 1;

        if (isfin) {
            // prefetch gx (overlaps dot warps' work for this step)
            float gxv = 0.f;
            if (lane < 24)
                gxv = g_gx[(size_t)t * (3 * H) + gx_lane_off];

            __syncthreads();   // partials[buf] for step t are complete

            float s = 0.f;
            if (lane < 24) {
                const float4* pr = (const float4*)(&partials[buf][lane][0]);
                float4 p0 = pr[0], p1 = pr[1], p2 = pr[2], p3 = pr[3];
                float4 p4 = pr[4], p5 = pr[5], p6 = pr[6], p7 = pr[7];
                float4 q0, q1, q2, q3, r0, r1, f;
                q0.x = p0.x + p1.x; q0.y = p0.y + p1.y; q0.z = p0.z + p1.z; q0.w = p0.w + p1.w;
                q1.x = p2.x + p3.x; q1.y = p2.y + p3.y; q1.z = p2.z + p3.z; q1.w = p2.w + p3.w;
                q2.x = p4.x + p5.x; q2.y = p4.y + p5.y; q2.z = p4.z + p5.z; q2.w = p4.w + p5.w;
                q3.x = p6.x + p7.x; q3.y = p6.y + p7.y; q3.z = p6.z + p7.z; q3.w = p6.w + p7.w;
                r0.x = q0.x + q1.x; r0.y = q0.y + q1.y; r0.z = q0.z + q1.z; r0.w = q0.w + q1.w;
                r1.x = q2.x + q3.x; r1.y = q2.y + q3.y; r1.z = q2.z + q3.z; r1.w = q2.w + q3.w;
                f.x = r0.x + r1.x; f.y = r0.y + r1.y; f.z = r0.z + r1.z; f.w = r0.w + r1.w;
                s = bh + ((f.x + f.y) + (f.z + f.w));
            }
            // lanes 0..15: r/z pre-activations include gx; lanes 16..23 keep
            // the hidden n-side separate (r gates only the hidden part)
            float val = s + ((lane < 16) ? gxv : 0.f);
            float sig = __fdividef(1.f, 1.f + __expf(-val));  // 24 parallel
            float v_n  = __shfl_sync(0xFFFFFFFFu, s,   o + 16);
            float gx_n = __shfl_sync(0xFFFFFFFFu, gxv, o + 16);
            float zz   = __shfl_sync(0xFFFFFFFFu, sig, o + 8);
            float hn = 0.f;
            if (lane < 8) {
                float r  = sig;
                float a  = gx_n + r * v_n;
                float e2 = __expf(2.f * a);
                float n  = 1.f - __fdividef(2.f, e2 + 1.f);   // tanh(a)
                hn = zz * (hprev - n) + n;                    // (1-z)*n + z*h
                hprev = hn;
            }
            // ---- publish: 24 packets (3 per replica x 8), no fence ----
            {
                const unsigned tagv = (unsigned)(t + 1);
                const int j   = lane - (lane / 3) * 3;   // lane % 3
                const int rep = lane / 3;                // 0..7 for lane<24
                int s0 = (3 * j)     & 31;
                int s1 = (3 * j + 1) & 31;
                int s2 = (3 * j + 2) & 31;
                float x = __shfl_sync(0xFFFFFFFFu, hn, s0);
                float y = __shfl_sync(0xFFFFFFFFu, hn, s1);
                float z = __shfl_sync(0xFFFFFFFFu, hn, s2);
                if (lane < 24) {
                    float* dst = &g_hline[(((size_t)rep * 2 + buf) * NSM + bid)
                                          * 32 + j * 4];
                    asm volatile(
                        "st.volatile.global.v4.f32 [%0], {%1, %2, %3, %4};"
                        :: "l"(dst), "f"(__uint_as_float(tagv)),
                           "f"(x), "f"(y), "f"(z) : "memory");
                }
            }
            // d_out write is off the critical path (nothing polls it)
            if (lane < 8)
                out[(size_t)t * H + obase + o] = hn;
        } else {
            // ---------------- dot warps ----------------
            unsigned long long h2[4];
            if (t == 0) {
#pragma unroll
                for (int q = 0; q < 4; ++q) h2[q] = 0ULL;
            } else {
                const int slot = (t - 1) & 1;
                if (g == 0) {
                    // fused poll+fetch on THIS CTA's replica of producer p's
                    // line; per-lane predicated (stop loading once seen)
                    const float* base =
                        g_hline + (((size_t)myrep * 2 + slot) * NSM + p) * 32;
                    const unsigned want = (unsigned)t;  // tag of h_{t-1}
                    float a0 = 0.f, a1 = 0.f, a2 = 0.f, a3 = 0.f;
                    float b0 = 0.f, b1 = 0.f, b2 = 0.f, b3 = 0.f;
                    float c0 = 0.f, c1 = 0.f, c2 = 0.f, c3 = 0.f;
                    bool ok = false;
                    do {
                        if (!ok) {
                            asm volatile(
                                "ld.volatile.global.v4.f32 {%0,%1,%2,%3}, [%4];"
                                : "=f"(a0), "=f"(a1), "=f"(a2), "=f"(a3)
                                : "l"(base));
                            asm volatile(
                                "ld.volatile.global.v4.f32 {%0,%1,%2,%3}, [%4];"
                                : "=f"(b0), "=f"(b1), "=f"(b2), "=f"(b3)
                                : "l"(base + 4));
                            asm volatile(
                                "ld.volatile.global.v4.f32 {%0,%1,%2,%3}, [%4];"
                                : "=f"(c0), "=f"(c1), "=f"(c2), "=f"(c3)
                                : "l"(base + 8));
                            ok = (__float_as_uint(a0) == want) &
                                 (__float_as_uint(b0) == want) &
                                 (__float_as_uint(c0) == want);
                        }
                    } while (!__all_sync(0xFFFFFFFFu, ok));
                    // h = {a1,a2,a3, b1,b2,b3, c1,c2}
                    float4 lo = make_float4(a1, a2, a3, b1);
                    float4 hi = make_float4(b2, b3, c1, c2);
                    *(float4*)&s_h[c][lane * 8]     = lo;
                    *(float4*)&s_h[c][lane * 8 + 4] = hi;
                    h2[0] = pack2(lo.x, lo.y);
                    h2[1] = pack2(lo.z, lo.w);
                    h2[2] = pack2(hi.x, hi.y);
                    h2[3] = pack2(hi.z, hi.w);
                    asm volatile("bar.sync %0, %1;" :: "r"(c + 1), "r"(128)
                                 : "memory");
                } else {
                    asm volatile("bar.sync %0, %1;" :: "r"(c + 1), "r"(128)
                                 : "memory");
                    float4 a = *(const float4*)&s_h[c][lane * 8];
                    float4 b = *(const float4*)&s_h[c][lane * 8 + 4];
                    h2[0] = pack2(a.x, a.y);
                    h2[1] = pack2(a.z, a.w);
                    h2[2] = pack2(b.x, b.y);
                    h2[3] = pack2(b.z, b.w);
                }
            }

            float accv[6];
#pragma unroll
            for (int j = 0; j < 6; ++j) {
                unsigned long long acc = 0ULL;
#pragma unroll
                for (int q = 0; q < 4; ++q) acc = ffma2(w2[j][q], h2[q], acc);
                accv[j] = hsum2(acc);
            }
#pragma unroll
            for (int j = 0; j < 6; ++j) {
                accv[j] += __shfl_xor_sync(0xFFFFFFFFu, accv[j], 16);
                accv[j] += __shfl_xor_sync(0xFFFFFFFFu, accv[j], 8);
            }
            if (lane < 8) {
#pragma unroll
                for (int j = 0; j < 6; ++j)
                    partials[buf][g * 6 + j][c * 8 + lane] = accv[j];
            }
            __syncthreads();   // release finalizer; dot warps head straight
                               // into step t+1's poll (parked siblings)
        }
    }
}

// ---------------------------------------------------------------------------
extern "C" void kernel_launch(void* const* d_in, const int* in_sizes, int n_in,
                              void* d_out, int out_size)
{
    const float* inp  = (const float*)d_in[0];  // [8192, 1024]
    const float* W_ih = (const float*)d_in[1];  // [3072, 1024]
    const float* W_hh = (const float*)d_in[2];  // [3072, 1024]
    const float* b_ih = (const float*)d_in[3];  // [3072]
    const float* b_hh = (const float*)d_in[4];  // [3072]
    float* out = (float*)d_out;                 // [8192, 1024]

    // 1) gx = inp @ W_ih^T + b_ih (block (0,0) also clears g_hline)
    dim3 ggrid(3072 / 128, S / 128);
    gemm_gx_kernel<<<ggrid, 256>>>(inp, W_ih, b_ih);

    // 2) persistent sequential GRU scan (one wave of 128 CTAs)
    gru_scan_kernel<<<NSM, SCAN_THREADS>>>(W_hh, b_hh, out);
}

// round 12
// speedup vs baseline: 1.0909x; 1.0909x over previous
#include <cuda_runtime.h>
#include <cstdint>

#define S 8192
#define H 1024
#define NSM 128
#define NWORK 24            // GEMM worker CTAs on spare SMs (GB300: 152 SMs)
#define SCAN_THREADS 544    // 16 dot-warps + finalizer warp 16 (highest wid)
#define NREP 4              // packet-line replicas (best measured, R10)
#define NTILE_N 24          // 3072 / 128
#define NTILE_M 64          // 8192 / 128
#define NTILES (NTILE_M * NTILE_N)

// Scratch: input-side gate projections gx[S][3H].
__device__ float g_gx[(size_t)S * 3 * H];
// h-exchange lines, replicated x4 and double buffered:
//   [rep][slot][producer][32 floats] = one 128B line per (rep,slot,producer).
// Three self-validating 16B packets per line:
//   [tag h0 h1 h2] [tag h3 h4 h5] [tag h6 h7 pad]  (tag = step+1 as uint bits)
__device__ __align__(128) float g_hline[NREP * 2 * NSM * 32];
// per-m-block gx completion counters, padded to one 128B line each
__device__ __align__(128) unsigned int g_gxready[NTILE_M * 32];
// work-stealing tile counter for the GEMM workers
__device__ unsigned int g_tilectr;

// ---------------------------------------------------------------------------
// packed fp32x2 helpers (sm_103a FFMA2 path)
// ---------------------------------------------------------------------------
__device__ __forceinline__ unsigned long long pack2(float lo, float hi) {
    unsigned long long r;
    asm("mov.b64 %0, {%1, %2};" : "=l"(r) : "f"(lo), "f"(hi));
    return r;
}
__device__ __forceinline__ unsigned long long ffma2(unsigned long long a,
                                                    unsigned long long b,
                                                    unsigned long long c) {
    unsigned long long d;
    asm("fma.rn.f32x2 %0, %1, %2, %3;" : "=l"(d) : "l"(a), "l"(b), "l"(c));
    return d;
}
__device__ __forceinline__ float hsum2(unsigned long long a) {
    float lo, hi;
    asm("mov.b64 {%0, %1}, %2;" : "=f"(lo), "=f"(hi) : "l"(a));
    return lo + hi;
}

// ---------------------------------------------------------------------------
// Kernel 1: clear exchange state for this graph replay (runs first, tiny).
// ---------------------------------------------------------------------------
__global__ void clear_kernel() {
    int idx = blockIdx.x * blockDim.x + threadIdx.x;   // 32*256 = 8192
    float4 z = make_float4(0.f, 0.f, 0.f, 0.f);
    ((float4*)g_hline)[idx] = z;                       // 8192 float4 total
    if (idx < NTILE_M * 32) g_gxready[idx] = 0u;
    if (idx == 0) g_tilectr = 0u;
}

// ---------------------------------------------------------------------------
// Kernel 2 (fused): bids 0..127 = persistent GRU scan (R10 protocol);
//                   bids 128..151 = persistent GEMM workers producing gx.
// ---------------------------------------------------------------------------
__global__ __launch_bounds__(SCAN_THREADS, 1) void fused_kernel(
    const float* __restrict__ A,      // inp [S,1024]
    const float* __restrict__ Wih,    // [3072,1024]
    const float* __restrict__ bih,    // [3072]
    const float* __restrict__ Whh,    // [3072,1024]
    const float* __restrict__ bhh,    // [3072]
    float* __restrict__ out)          // [S,1024]
{
    const int tid  = threadIdx.x;
    const int warp = tid >> 5;
    const int lane = tid & 31;
    const int bid  = blockIdx.x;

    if (bid >= NSM) {
        // ================= GEMM worker: gx = inp @ Wih^T + bih =============
        __shared__ __align__(16) float As[16][132];
        __shared__ __align__(16) float Bs[16][132];
        __shared__ int s_tile;
        const bool act = (tid < 256);
        const int tx = tid & 15;
        const int ty = (tid >> 4) & 15;

        for (;;) {
            if (tid == 0) s_tile = (int)atomicAdd(&g_tilectr, 1u);
            __syncthreads();
            const int ti = s_tile;
            if (ti >= NTILES) break;
            const int mb = ti / NTILE_N;
            const int m0 = mb * 128;
            const int n0 = (ti - mb * NTILE_N) * 128;

            unsigned long long acc2[8][4];
#pragma unroll
            for (int i = 0; i < 8; ++i)
#pragma unroll
                for (int q = 0; q < 4; ++q) acc2[i][q] = 0ULL;

            for (int kt = 0; kt < 1024; kt += 16) {
                if (act) {
#pragma unroll
                    for (int r = 0; r < 2; ++r) {
                        int idx = tid + r * 256;
                        int row = idx >> 2;
                        int kq  = idx & 3;
                        float4 v = *(const float4*)(A + (size_t)(m0 + row) * 1024 + kt + kq * 4);
                        As[kq * 4 + 0][row] = v.x;
                        As[kq * 4 + 1][row] = v.y;
                        As[kq * 4 + 2][row] = v.z;
                        As[kq * 4 + 3][row] = v.w;
                    }
#pragma unroll
                    for (int r = 0; r < 2; ++r) {
                        int idx = tid + r * 256;
                        int n  = idx >> 2;
                        int kq = idx & 3;
                        float4 v = *(const float4*)(Wih + (size_t)(n0 + n) * 1024 + kt + kq * 4);
                        Bs[kq * 4 + 0][n] = v.x;
                        Bs[kq * 4 + 1][n] = v.y;
                        Bs[kq * 4 + 2][n] = v.z;
                        Bs[kq * 4 + 3][n] = v.w;
                    }
                }
                __syncthreads();
                if (act) {
#pragma unroll
                    for (int k = 0; k < 16; ++k) {
                        float4 b0 = *(const float4*)&Bs[k][tx * 8];
                        float4 b1 = *(const float4*)&Bs[k][tx * 8 + 4];
                        unsigned long long rb2[4];
                        rb2[0] = pack2(b0.x, b0.y);
                        rb2[1] = pack2(b0.z, b0.w);
                        rb2[2] = pack2(b1.x, b1.y);
                        rb2[3] = pack2(b1.z, b1.w);
#pragma unroll
                        for (int i = 0; i < 8; ++i) {
                            float a = As[k][ty * 8 + i];
                            unsigned long long a2 = pack2(a, a);
#pragma unroll
                            for (int q = 0; q < 4; ++q)
                                acc2[i][q] = ffma2(a2, rb2[q], acc2[i][q]);
                        }
                    }
                }
                __syncthreads();
            }

            if (act) {
#pragma unroll
                for (int i = 0; i < 8; ++i) {
                    size_t rowoff = (size_t)(m0 + ty * 8 + i) * 3072 + n0 + tx * 8;
#pragma unroll
                    for (int jq = 0; jq < 2; ++jq) {
                        float lo0, hi0, lo1, hi1;
                        asm("mov.b64 {%0, %1}, %2;" : "=f"(lo0), "=f"(hi0) : "l"(acc2[i][jq * 2 + 0]));
                        asm("mov.b64 {%0, %1}, %2;" : "=f"(lo1), "=f"(hi1) : "l"(acc2[i][jq * 2 + 1]));
                        float4 v;
                        v.x = lo0 + bih[n0 + tx * 8 + jq * 4 + 0];
                        v.y = hi0 + bih[n0 + tx * 8 + jq * 4 + 1];
                        v.z = lo1 + bih[n0 + tx * 8 + jq * 4 + 2];
                        v.w = hi1 + bih[n0 + tx * 8 + jq * 4 + 3];
                        *(float4*)(g_gx + rowoff + jq * 4) = v;
                    }
                }
            }
            __threadfence();     // make this thread's gx stores GPU-visible
            __syncthreads();     // all threads' fences done before the flag
            if (tid == 0) {
                asm volatile("red.release.gpu.global.add.u32 [%0], 1;"
                             :: "l"(&g_gxready[mb * 32]) : "memory");
            }
        }
        return;
    }

    // ==================== persistent GRU scan (R10 protocol) ===============
    const int obase = bid * 8;

    __shared__ __align__(16) float s_h[4][256];        // per-chunk h relay
    __shared__ __align__(16) float partials[2][24][36];

    const bool isfin = (warp == 16);
    const int c = warp & 3;              // k-chunk (0..3): leaders on SMSP 0..3
    const int g = warp >> 2;             // row-group (0..3)
    const int k0 = c * 256 + lane * 8;
    const int p  = c * 32 + lane;        // producer this lane covers (g==0)
    const int myrep = bid & (NREP - 1);  // replica this CTA polls

    // ---- dot-warp setup: 6 gate-rows x 8 cols of W_hh, packed f32x2 ----
    unsigned long long w2[6][4];
    if (!isfin) {
#pragma unroll
        for (int j = 0; j < 6; ++j) {
            int gr  = g * 6 + j;                          // 0..23
            int row = (gr >> 3) * H + obase + (gr & 7);   // gate*H + out idx
            const float4* pw = (const float4*)(Whh + (size_t)row * H + k0);
            float4 a = pw[0], b = pw[1];
            w2[j][0] = pack2(a.x, a.y);
            w2[j][1] = pack2(a.z, a.w);
            w2[j][2] = pack2(b.x, b.y);
            w2[j][3] = pack2(b.z, b.w);
        }
    }

    // ---- finalizer setup ----
    const int o = lane & 7;
    float bh = 0.f;
    if (isfin && lane < 24) bh = bhh[(lane >> 3) * H + obase + o];
    float hprev = 0.f;                   // lanes 0..7 carry h for their dim
    const size_t gx_lane_off = (size_t)(lane >> 3) * H + obase + o;

    for (int t = 0; t < S; ++t) {
        const int buf = t & 1;

        if (isfin) {
            // gate on gx availability once per m-block (128 steps);
            // broadcast acquire-load: one sector per warp per iteration
            if ((t & 127) == 0) {
                const unsigned int* rp = &g_gxready[(t >> 7) * 32];
                unsigned int v;
                do {
                    asm volatile("ld.acquire.gpu.global.u32 %0, [%1];"
                                 : "=r"(v) : "l"(rp) : "memory");
                } while (v < (unsigned)NTILE_N);
            }
            // prefetch gx (L2, bypass L1 -- written by worker SMs)
            float gxv = 0.f;
            if (lane < 24)
                gxv = __ldcg(&g_gx[(size_t)t * (3 * H) + gx_lane_off]);

            __syncthreads();   // partials[buf] for step t are complete

            float s = 0.f;
            if (lane < 24) {
                const float4* pr = (const float4*)(&partials[buf][lane][0]);
                float4 p0 = pr[0], p1 = pr[1], p2 = pr[2], p3 = pr[3];
                float4 p4 = pr[4], p5 = pr[5], p6 = pr[6], p7 = pr[7];
                float4 q0, q1, q2, q3, r0, r1, f;
                q0.x = p0.x + p1.x; q0.y = p0.y + p1.y; q0.z = p0.z + p1.z; q0.w = p0.w + p1.w;
                q1.x = p2.x + p3.x; q1.y = p2.y + p3.y; q1.z = p2.z + p3.z; q1.w = p2.w + p3.w;
                q2.x = p4.x + p5.x; q2.y = p4.y + p5.y; q2.z = p4.z + p5.z; q2.w = p4.w + p5.w;
                q3.x = p6.x + p7.x; q3.y = p6.y + p7.y; q3.z = p6.z + p7.z; q3.w = p6.w + p7.w;
                r0.x = q0.x + q1.x; r0.y = q0.y + q1.y; r0.z = q0.z + q1.z; r0.w = q0.w + q1.w;
                r1.x = q2.x + q3.x; r1.y = q2.y + q3.y; r1.z = q2.z + q3.z; r1.w = q2.w + q3.w;
                f.x = r0.x + r1.x; f.y = r0.y + r1.y; f.z = r0.z + r1.z; f.w = r0.w + r1.w;
                s = bh + ((f.x + f.y) + (f.z + f.w));
            }
            // lanes 0..15: r/z pre-activations include gx; lanes 16..23 keep
            // the hidden n-side separate (r gates only the hidden part)
            float val = s + ((lane < 16) ? gxv : 0.f);
            float sig = __fdividef(1.f, 1.f + __expf(-val));  // 24 parallel
            float v_n  = __shfl_sync(0xFFFFFFFFu, s,   o + 16);
            float gx_n = __shfl_sync(0xFFFFFFFFu, gxv, o + 16);
            float zz   = __shfl_sync(0xFFFFFFFFu, sig, o + 8);
            float hn = 0.f;
            if (lane < 8) {
                float r  = sig;
                float a  = gx_n + r * v_n;
                float e2 = __expf(2.f * a);
                float n  = 1.f - __fdividef(2.f, e2 + 1.f);   // tanh(a)
                hn = zz * (hprev - n) + n;                    // (1-z)*n + z*h
                hprev = hn;
            }
            // ---- publish: 12 packets (3 per replica x 4), no fence ----
            {
                const unsigned tagv = (unsigned)(t + 1);
                const int j   = lane - (lane / 3) * 3;   // lane % 3
                const int rep = lane / 3;                // 0..3 for lane<12
                int s0 = (3 * j)     & 31;
                int s1 = (3 * j + 1) & 31;
                int s2 = (3 * j + 2) & 31;
                float x = __shfl_sync(0xFFFFFFFFu, hn, s0);
                float y = __shfl_sync(0xFFFFFFFFu, hn, s1);
                float z = __shfl_sync(0xFFFFFFFFu, hn, s2);
                if (lane < 12) {
                    float* dst = &g_hline[(((size_t)rep * 2 + buf) * NSM + bid)
                                          * 32 + j * 4];
                    asm volatile(
                        "st.volatile.global.v4.f32 [%0], {%1, %2, %3, %4};"
                        :: "l"(dst), "f"(__uint_as_float(tagv)),
                           "f"(x), "f"(y), "f"(z) : "memory");
                }
            }
            // d_out write is off the critical path (nothing polls it)
            if (lane < 8)
                out[(size_t)t * H + obase + o] = hn;
        } else {
            // ---------------- dot warps ----------------
            unsigned long long h2[4];
            if (t == 0) {
#pragma unroll
                for (int q = 0; q < 4; ++q) h2[q] = 0ULL;
            } else {
                const int slot = (t - 1) & 1;
                if (g == 0) {
                    // fused poll+fetch on THIS CTA's replica of producer p's
                    // line; per-lane predicated (stop loading once seen)
                    const float* base =
                        g_hline + (((size_t)myrep * 2 + slot) * NSM + p) * 32;
                    const unsigned want = (unsigned)t;  // tag of h_{t-1}
                    float a0 = 0.f, a1 = 0.f, a2 = 0.f, a3 = 0.f;
                    float b0 = 0.f, b1 = 0.f, b2 = 0.f, b3 = 0.f;
                    float c0 = 0.f, c1 = 0.f, c2 = 0.f, c3 = 0.f;
                    bool ok = false;
                    do {
                        if (!ok) {
                            asm volatile(
                                "ld.volatile.global.v4.f32 {%0,%1,%2,%3}, [%4];"
                                : "=f"(a0), "=f"(a1), "=f"(a2), "=f"(a3)
                                : "l"(base));
                            asm volatile(
                                "ld.volatile.global.v4.f32 {%0,%1,%2,%3}, [%4];"
                                : "=f"(b0), "=f"(b1), "=f"(b2), "=f"(b3)
                                : "l"(base + 4));
                            asm volatile(
                                "ld.volatile.global.v4.f32 {%0,%1,%2,%3}, [%4];"
                                : "=f"(c0), "=f"(c1), "=f"(c2), "=f"(c3)
                                : "l"(base + 8));
                            ok = (__float_as_uint(a0) == want) &
                                 (__float_as_uint(b0) == want) &
                                 (__float_as_uint(c0) == want);
                        }
                    } while (!__all_sync(0xFFFFFFFFu, ok));
                    // h = {a1,a2,a3, b1,b2,b3, c1,c2}
                    float4 lo = make_float4(a1, a2, a3, b1);
                    float4 hi = make_float4(b2, b3, c1, c2);
                    *(float4*)&s_h[c][lane * 8]     = lo;
                    *(float4*)&s_h[c][lane * 8 + 4] = hi;
                    h2[0] = pack2(lo.x, lo.y);
                    h2[1] = pack2(lo.z, lo.w);
                    h2[2] = pack2(hi.x, hi.y);
                    h2[3] = pack2(hi.z, hi.w);
                    asm volatile("bar.sync %0, %1;" :: "r"(c + 1), "r"(128)
                                 : "memory");
                } else {
                    asm volatile("bar.sync %0, %1;" :: "r"(c + 1), "r"(128)
                                 : "memory");
                    float4 a = *(const float4*)&s_h[c][lane * 8];
                    float4 b = *(const float4*)&s_h[c][lane * 8 + 4];
                    h2[0] = pack2(a.x, a.y);
                    h2[1] = pack2(a.z, a.w);
                    h2[2] = pack2(b.x, b.y);
                    h2[3] = pack2(b.z, b.w);
                }
            }

            float accv[6];
#pragma unroll
            for (int j = 0; j < 6; ++j) {
                unsigned long long acc = 0ULL;
#pragma unroll
                for (int q = 0; q < 4; ++q) acc = ffma2(w2[j][q], h2[q], acc);
                accv[j] = hsum2(acc);
            }
#pragma unroll
            for (int j = 0; j < 6; ++j) {
                accv[j] += __shfl_xor_sync(0xFFFFFFFFu, accv[j], 16);
                accv[j] += __shfl_xor_sync(0xFFFFFFFFu, accv[j], 8);
            }
            if (lane < 8) {
#pragma unroll
                for (int j = 0; j < 6; ++j)
                    partials[buf][g * 6 + j][c * 8 + lane] = accv[j];
            }
            __syncthreads();   // release finalizer; dot warps head straight
                               // into step t+1's poll (parked siblings)
        }
    }
}

// ---------------------------------------------------------------------------
extern "C" void kernel_launch(void* const* d_in, const int* in_sizes, int n_in,
                              void* d_out, int out_size)
{
    const float* inp  = (const float*)d_in[0];  // [8192, 1024]
    const float* W_ih = (const float*)d_in[1];  // [3072, 1024]
    const float* W_hh = (const float*)d_in[2];  // [3072, 1024]
    const float* b_ih = (const float*)d_in[3];  // [3072]
    const float* b_hh = (const float*)d_in[4];  // [3072]
    float* out = (float*)d_out;                 // [8192, 1024]

    // 1) reset exchange state (tags, gx-ready counters, tile counter)
    clear_kernel<<<32, 256>>>();

    // 2) fused: 128 scan CTAs + 24 work-stealing GEMM CTAs, one wave
    fused_kernel<<<NSM + NWORK, SCAN_THREADS>>>(inp, W_ih, b_ih,
                                                W_hh, b_hh, out);
}